// round 9
// baseline (speedup 1.0000x reference)
#include <cuda_runtime.h>
#include <cstddef>
#include <cstdint>

#define EPS 1e-8f

static constexpr int B    = 1024;
static constexpr int K    = 512;
static constexpr int E    = 64;
static constexpr int D    = 769;
static constexpr int TOPK = 64;

static constexpr int NCHUNK = 4;
static constexpr int CB     = B / NCHUNK;   // 256 rows per chunk

__device__ float g_aw[B * E];      // normalized anchor weights a
__device__ float g_la[B * E];      // log(a + EPS) via XLA-CPU log
__device__ float g_scores[B * K];
__device__ int   g_idx[B * TOPK];

// ---------------------------------------------------------------------------
// Bit-exact replica of XLA-CPU's GenerateVF32Log (Eigen plog / Cephes):
// NO FMA contraction, exact operation order. DO NOT MODIFY.
// ---------------------------------------------------------------------------
__device__ __forceinline__ float xla_logf(float xin) {
    float x = fmaxf(xin, __uint_as_float(0x00800000u));
    uint32_t bits = __float_as_uint(x);
    int emm0 = (int)(bits >> 23) - 126;
    float e = (float)emm0;
    float m = __uint_as_float((bits & 0x807fffffu) | 0x3f000000u);
    bool mask = m < __uint_as_float(0x3f3504f3u);
    float tmp = mask ? m : 0.0f;
    float xx = __fadd_rn(__fsub_rn(m, 1.0f), tmp);
    e = __fsub_rn(e, mask ? 1.0f : 0.0f);

    float z = __fmul_rn(xx, xx);
    float y = 7.0376836292e-2f;
    y = __fadd_rn(__fmul_rn(y, xx), -1.1514610310e-1f);
    y = __fadd_rn(__fmul_rn(y, xx),  1.1676998740e-1f);
    y = __fadd_rn(__fmul_rn(y, xx), -1.2420140846e-1f);
    y = __fadd_rn(__fmul_rn(y, xx),  1.4249322787e-1f);
    y = __fadd_rn(__fmul_rn(y, xx), -1.6668057665e-1f);
    y = __fadd_rn(__fmul_rn(y, xx),  2.0000714765e-1f);
    y = __fadd_rn(__fmul_rn(y, xx), -2.4999993993e-1f);
    y = __fadd_rn(__fmul_rn(y, xx),  3.3333331174e-1f);
    y = __fmul_rn(y, xx);
    y = __fmul_rn(y, z);
    y = __fadd_rn(y, __fmul_rn(e, -2.12194440e-4f));
    y = __fsub_rn(y, __fmul_rn(z, 0.5f));
    float r = __fadd_rn(xx, y);
    r = __fadd_rn(r, __fmul_rn(e, 0.693359375f));
    return r;
}

#define NEON_HORIZ(a0, a1, a2, a3) __fadd_rn(__fadd_rn(a0, a2), __fadd_rn(a1, a3))

// ---------------------------------------------------------------------------
// K1: anchor rows. One thread per b, XLA-CPU op order. (unchanged, passing)
// ---------------------------------------------------------------------------
__global__ __launch_bounds__(256) void k_anchor(const float* __restrict__ anchor) {
    int b = blockIdx.x * blockDim.x + threadIdx.x;
    if (b >= B) return;
    const float4* row = (const float4*)(anchor + b * E);
    float4 vv[16];
    float a0 = 0.f, a1 = 0.f, a2 = 0.f, a3 = 0.f;
    #pragma unroll
    for (int c = 0; c < 16; c++) {
        vv[c] = __ldg(row + c);
        a0 = __fadd_rn(a0, __fadd_rn(vv[c].x, EPS));
        a1 = __fadd_rn(a1, __fadd_rn(vv[c].y, EPS));
        a2 = __fadd_rn(a2, __fadd_rn(vv[c].z, EPS));
        a3 = __fadd_rn(a3, __fadd_rn(vv[c].w, EPS));
    }
    float S = NEON_HORIZ(a0, a1, a2, a3);
    const float* vf = (const float*)vv;
    #pragma unroll
    for (int e = 0; e < E; e++) {
        float a = __fdiv_rn(__fadd_rn(vf[e], EPS), S);
        g_aw[b * E + e] = a;
        g_la[b * E + e] = xla_logf(__fadd_rn(a, EPS));
    }
}

// ---------------------------------------------------------------------------
// K2: confusion scores (chunked). Arithmetic op-identical to passing R5/R7.
// ---------------------------------------------------------------------------
__global__ __launch_bounds__(256, 5) void k_scores(
    const float* __restrict__ neg, int row_off)
{
    __shared__ float s_a[E], s_la[E];
    int b = row_off + (blockIdx.x >> 1);
    int k = ((blockIdx.x & 1) << 8) + threadIdx.x;
    if (threadIdx.x < E) {
        s_a[threadIdx.x]  = g_aw[b * E + threadIdx.x];
        s_la[threadIdx.x] = g_la[b * E + threadIdx.x];
    }
    __syncthreads();

    const float4* row = (const float4*)(neg + ((size_t)b * K + k) * E);

    float a0 = 0.f, a1 = 0.f, a2 = 0.f, a3 = 0.f;
    #pragma unroll
    for (int c = 0; c < 16; c++) {
        float4 v;
        asm volatile("ld.global.nc.v4.f32 {%0,%1,%2,%3}, [%4];"
                     : "=f"(v.x), "=f"(v.y), "=f"(v.z), "=f"(v.w)
                     : "l"(row + c));
        a0 = __fadd_rn(a0, __fadd_rn(v.x, EPS));
        a1 = __fadd_rn(a1, __fadd_rn(v.y, EPS));
        a2 = __fadd_rn(a2, __fadd_rn(v.z, EPS));
        a3 = __fadd_rn(a3, __fadd_rn(v.w, EPS));
    }
    float S = NEON_HORIZ(a0, a1, a2, a3);

    float k0 = 0.f, k1 = 0.f, k2 = 0.f, k3 = 0.f;
    #pragma unroll 4
    for (int c = 0; c < 16; c++) {
        float4 v = __ldg(row + c);
        int e = 4 * c;
        float nn0 = __fdiv_rn(__fadd_rn(v.x, EPS), S);
        float nn1 = __fdiv_rn(__fadd_rn(v.y, EPS), S);
        float nn2 = __fdiv_rn(__fadd_rn(v.z, EPS), S);
        float nn3 = __fdiv_rn(__fadd_rn(v.w, EPS), S);
        float ln0 = xla_logf(__fadd_rn(nn0, EPS));
        float ln1 = xla_logf(__fadd_rn(nn1, EPS));
        float ln2 = xla_logf(__fadd_rn(nn2, EPS));
        float ln3 = xla_logf(__fadd_rn(nn3, EPS));
        k0 = __fadd_rn(k0, __fmul_rn(s_a[e+0], __fsub_rn(s_la[e+0], ln0)));
        k1 = __fadd_rn(k1, __fmul_rn(s_a[e+1], __fsub_rn(s_la[e+1], ln1)));
        k2 = __fadd_rn(k2, __fmul_rn(s_a[e+2], __fsub_rn(s_la[e+2], ln2)));
        k3 = __fadd_rn(k3, __fmul_rn(s_a[e+3], __fsub_rn(s_la[e+3], ln3)));
    }
    g_scores[b * K + k] = -NEON_HORIZ(k0, k1, k2, k3);
}

// ---------------------------------------------------------------------------
// K3: top-64 via bitonic sort of 512 (desc, ties -> lower index). Chunked.
// ---------------------------------------------------------------------------
__global__ __launch_bounds__(512) void k_topk(
    float* __restrict__ out_scores, int row_off)
{
    __shared__ float ss[K];
    __shared__ int   si[K];
    int b = row_off + blockIdx.x, tid = threadIdx.x;
    ss[tid] = g_scores[b * K + tid];
    si[tid] = tid;
    for (int sz = 2; sz <= K; sz <<= 1) {
        for (int j = sz >> 1; j > 0; j >>= 1) {
            __syncthreads();
            int ixj = tid ^ j;
            if (ixj > tid) {
                bool desc = ((tid & sz) == 0);
                float s1 = ss[tid], s2 = ss[ixj];
                int   i1 = si[tid], i2 = si[ixj];
                bool g = (s1 > s2) || (s1 == s2 && i1 < i2);
                if (g != desc) {
                    ss[tid] = s2; ss[ixj] = s1;
                    si[tid] = i2; si[ixj] = i1;
                }
            }
        }
    }
    __syncthreads();
    if (tid < TOPK) {
        out_scores[b * TOPK + tid] = ss[tid];
        g_idx[b * TOPK + tid]      = si[tid];
    }
}

// ---------------------------------------------------------------------------
// K4: gather selected candidate rows (769 f32) — coalesced copy. Chunked.
// ---------------------------------------------------------------------------
__global__ __launch_bounds__(128) void k_gather(
    const float* __restrict__ cand, float* __restrict__ out_hard, int row_off)
{
    int blk = blockIdx.x;
    int b = row_off + (blk >> 6), j = blk & (TOPK - 1);
    int idx = g_idx[b * TOPK + j];
    const float* __restrict__ src = cand + ((size_t)b * K + idx) * D;
    float* __restrict__ dst = out_hard + ((size_t)b * TOPK + j) * D;
    #pragma unroll
    for (int i = threadIdx.x; i < D; i += 128)
        dst[i] = __ldg(src + i);
}

// ---------------------------------------------------------------------------
// Fork-join pipeline: scores/topk chunks on the origin stream, gathers on a
// side stream joined by events -> gather(chunk i) overlaps scores(chunk i+1).
// Stream/event objects are host-side only (no device memory); kernel_launch
// is invoked only for correctness + capture, so per-call creation is fine.
// ---------------------------------------------------------------------------
extern "C" void kernel_launch(void* const* d_in, const int* in_sizes, int n_in,
                              void* d_out, int out_size) {
    const float* anchor = (const float*)d_in[0];  // (B, E)
    const float* neg    = (const float*)d_in[1];  // (B, K, E)
    const float* cand   = (const float*)d_in[2];  // (B, K, D)
    float* out        = (float*)d_out;
    float* out_hard   = out;                          // (B, TOPK, D)
    float* out_scores = out + (size_t)B * TOPK * D;   // (B, TOPK)

    cudaStream_t s1;
    cudaStreamCreateWithFlags(&s1, cudaStreamNonBlocking);

    k_anchor<<<4, 256>>>(anchor);

    cudaEvent_t ev[NCHUNK];
    for (int c = 0; c < NCHUNK; c++) {
        int row_off = c * CB;
        k_scores<<<CB * 2, 256>>>(neg, row_off);
        k_topk<<<CB, 512>>>(out_scores, row_off);
        cudaEventCreateWithFlags(&ev[c], cudaEventDisableTiming);
        cudaEventRecord(ev[c], 0);
        cudaStreamWaitEvent(s1, ev[c], 0);
        k_gather<<<CB * TOPK, 128, 0, s1>>>(cand, out_hard, row_off);
    }

    // join the side stream back into the origin stream
    cudaEvent_t evj;
    cudaEventCreateWithFlags(&evj, cudaEventDisableTiming);
    cudaEventRecord(evj, s1);
    cudaStreamWaitEvent(0, evj, 0);
}

// round 10
// speedup vs baseline: 1.1699x; 1.1699x over previous
#include <cuda_runtime.h>
#include <cstddef>
#include <cstdint>

#define EPS 1e-8f

static constexpr int B    = 1024;
static constexpr int K    = 512;
static constexpr int E    = 64;
static constexpr int D    = 769;
static constexpr int TOPK = 64;

// pipeline layout: 16 superblocks of 64 rows
// SB0: 128 score CTAs; SB s(1..15): 128 score (chunk s) + 32 row (chunk s-1);
// tail: 32 row CTAs (chunk 15). Row CTA = 2 batch rows.
static constexpr int GRID_PIPE = 2560;

__device__ float g_aw[B * E];
__device__ float g_la[B * E];
__device__ float g_scores[B * K];
__device__ int   g_cnt[B];          // zero-init; reset by consumer each run

// ---------------------------------------------------------------------------
// Bit-exact replica of XLA-CPU's GenerateVF32Log (Eigen plog / Cephes):
// NO FMA contraction, exact operation order. DO NOT MODIFY.
// ---------------------------------------------------------------------------
__device__ __forceinline__ float xla_logf(float xin) {
    float x = fmaxf(xin, __uint_as_float(0x00800000u));
    uint32_t bits = __float_as_uint(x);
    int emm0 = (int)(bits >> 23) - 126;
    float e = (float)emm0;
    float m = __uint_as_float((bits & 0x807fffffu) | 0x3f000000u);
    bool mask = m < __uint_as_float(0x3f3504f3u);
    float tmp = mask ? m : 0.0f;
    float xx = __fadd_rn(__fsub_rn(m, 1.0f), tmp);
    e = __fsub_rn(e, mask ? 1.0f : 0.0f);

    float z = __fmul_rn(xx, xx);
    float y = 7.0376836292e-2f;
    y = __fadd_rn(__fmul_rn(y, xx), -1.1514610310e-1f);
    y = __fadd_rn(__fmul_rn(y, xx),  1.1676998740e-1f);
    y = __fadd_rn(__fmul_rn(y, xx), -1.2420140846e-1f);
    y = __fadd_rn(__fmul_rn(y, xx),  1.4249322787e-1f);
    y = __fadd_rn(__fmul_rn(y, xx), -1.6668057665e-1f);
    y = __fadd_rn(__fmul_rn(y, xx),  2.0000714765e-1f);
    y = __fadd_rn(__fmul_rn(y, xx), -2.4999993993e-1f);
    y = __fadd_rn(__fmul_rn(y, xx),  3.3333331174e-1f);
    y = __fmul_rn(y, xx);
    y = __fmul_rn(y, z);
    y = __fadd_rn(y, __fmul_rn(e, -2.12194440e-4f));
    y = __fsub_rn(y, __fmul_rn(z, 0.5f));
    float r = __fadd_rn(xx, y);
    r = __fadd_rn(r, __fmul_rn(e, 0.693359375f));
    return r;
}

#define NEON_HORIZ(a0, a1, a2, a3) __fadd_rn(__fadd_rn(a0, a2), __fadd_rn(a1, a3))

__device__ __forceinline__ int ld_acquire(const int* p) {
    int v;
    asm volatile("ld.acquire.gpu.global.b32 %0, [%1];" : "=r"(v) : "l"(p) : "memory");
    return v;
}

// ---------------------------------------------------------------------------
// K1: anchor rows (proven, unchanged).
// ---------------------------------------------------------------------------
__global__ __launch_bounds__(256) void k_anchor(const float* __restrict__ anchor) {
    int b = blockIdx.x * blockDim.x + threadIdx.x;
    if (b >= B) return;
    const float4* row = (const float4*)(anchor + b * E);
    float4 vv[16];
    float a0 = 0.f, a1 = 0.f, a2 = 0.f, a3 = 0.f;
    #pragma unroll
    for (int c = 0; c < 16; c++) {
        vv[c] = __ldg(row + c);
        a0 = __fadd_rn(a0, __fadd_rn(vv[c].x, EPS));
        a1 = __fadd_rn(a1, __fadd_rn(vv[c].y, EPS));
        a2 = __fadd_rn(a2, __fadd_rn(vv[c].z, EPS));
        a3 = __fadd_rn(a3, __fadd_rn(vv[c].w, EPS));
    }
    float S = NEON_HORIZ(a0, a1, a2, a3);
    const float* vf = (const float*)vv;
    #pragma unroll
    for (int e = 0; e < E; e++) {
        float a = __fdiv_rn(__fadd_rn(vf[e], EPS), S);
        g_aw[b * E + e] = a;
        g_la[b * E + e] = xla_logf(__fadd_rn(a, EPS));
    }
}

// ---------------------------------------------------------------------------
// K2 (pipelined): score CTAs + row CTAs (sort + vectorized gather) in one
// grid, interleaved by bid so DRAM-bound gather overlaps FMA-bound scores.
// ---------------------------------------------------------------------------
__global__ __launch_bounds__(256, 5) void k_pipe(
    const float* __restrict__ neg, const float* __restrict__ cand,
    float* __restrict__ out_hard, float* __restrict__ out_scores)
{
    __shared__ float s_a[E], s_la[E];
    __shared__ float ss[K];
    __shared__ int   si[K];
    __shared__ float buf[8][776];    // per-warp staging for realigned copy

    int bid = blockIdx.x;
    int tid = threadIdx.x;

    // ---- bid decode ------------------------------------------------------
    int type, chunk, idx;
    if (bid < 128)        { type = 0; chunk = 0; idx = bid; }
    else if (bid < 2528)  {
        int g = bid - 128, s = g / 160, r = g % 160;
        if (r < 128) { type = 0; chunk = s + 1; idx = r; }
        else         { type = 1; chunk = s;     idx = r - 128; }
    }
    else                  { type = 1; chunk = 15; idx = bid - 2528; }

    if (type == 0) {
        // ================= SCORE CTA (exact R7 arithmetic) ================
        int b = chunk * 64 + (idx >> 1);
        int k = ((idx & 1) << 8) + tid;
        if (tid < E) {
            s_a[tid]  = g_aw[b * E + tid];
            s_la[tid] = g_la[b * E + tid];
        }
        __syncthreads();

        const float4* row = (const float4*)(neg + ((size_t)b * K + k) * E);

        float a0 = 0.f, a1 = 0.f, a2 = 0.f, a3 = 0.f;
        #pragma unroll
        for (int c = 0; c < 16; c++) {
            float4 v;
            asm volatile("ld.global.nc.v4.f32 {%0,%1,%2,%3}, [%4];"
                         : "=f"(v.x), "=f"(v.y), "=f"(v.z), "=f"(v.w)
                         : "l"(row + c));
            a0 = __fadd_rn(a0, __fadd_rn(v.x, EPS));
            a1 = __fadd_rn(a1, __fadd_rn(v.y, EPS));
            a2 = __fadd_rn(a2, __fadd_rn(v.z, EPS));
            a3 = __fadd_rn(a3, __fadd_rn(v.w, EPS));
        }
        float S = NEON_HORIZ(a0, a1, a2, a3);

        float k0 = 0.f, k1 = 0.f, k2 = 0.f, k3 = 0.f;
        #pragma unroll 4
        for (int c = 0; c < 16; c++) {
            float4 v = __ldg(row + c);
            int e = 4 * c;
            float nn0 = __fdiv_rn(__fadd_rn(v.x, EPS), S);
            float nn1 = __fdiv_rn(__fadd_rn(v.y, EPS), S);
            float nn2 = __fdiv_rn(__fadd_rn(v.z, EPS), S);
            float nn3 = __fdiv_rn(__fadd_rn(v.w, EPS), S);
            float ln0 = xla_logf(__fadd_rn(nn0, EPS));
            float ln1 = xla_logf(__fadd_rn(nn1, EPS));
            float ln2 = xla_logf(__fadd_rn(nn2, EPS));
            float ln3 = xla_logf(__fadd_rn(nn3, EPS));
            k0 = __fadd_rn(k0, __fmul_rn(s_a[e+0], __fsub_rn(s_la[e+0], ln0)));
            k1 = __fadd_rn(k1, __fmul_rn(s_a[e+1], __fsub_rn(s_la[e+1], ln1)));
            k2 = __fadd_rn(k2, __fmul_rn(s_a[e+2], __fsub_rn(s_la[e+2], ln2)));
            k3 = __fadd_rn(k3, __fmul_rn(s_a[e+3], __fsub_rn(s_la[e+3], ln3)));
        }
        g_scores[b * K + k] = -NEON_HORIZ(k0, k1, k2, k3);

        __syncthreads();                       // all 256 scores written
        if (tid == 0) {
            __threadfence();                   // publish (release)
            atomicAdd(&g_cnt[b], 1);
        }
    } else {
        // ================= ROW CTA: topk + gather for 2 rows ==============
        int warp = tid >> 5, lane = tid & 31;
        for (int rr = 0; rr < 2; rr++) {
            int b = chunk * 64 + idx * 2 + rr;

            if (tid == 0) {
                while (ld_acquire(&g_cnt[b]) < 2) __nanosleep(200);
            }
            __syncthreads();

            ss[tid]       = g_scores[b * K + tid];
            ss[tid + 256] = g_scores[b * K + tid + 256];
            si[tid]       = tid;
            si[tid + 256] = tid + 256;

            // bitonic sort of 512 (desc, ties -> lower index), 1 pair/thread
            for (int sz = 2; sz <= K; sz <<= 1) {
                for (int j = sz >> 1; j > 0; j >>= 1) {
                    __syncthreads();
                    int i   = ((tid & ~(j - 1)) << 1) | (tid & (j - 1));
                    int ixj = i + j;
                    bool desc = ((i & sz) == 0);
                    float s1 = ss[i], s2 = ss[ixj];
                    int   i1 = si[i], i2 = si[ixj];
                    bool g = (s1 > s2) || (s1 == s2 && i1 < i2);
                    if (g != desc) {
                        ss[i] = s2; ss[ixj] = s1;
                        si[i] = i2; si[ixj] = i1;
                    }
                }
            }
            __syncthreads();

            if (tid < TOPK) out_scores[b * TOPK + tid] = ss[tid];

            // vectorized gather: warp w copies selected rows w, w+8, ...
            for (int j = warp; j < TOPK; j += 8) {
                int sidx = si[j];
                size_t sbase = ((size_t)b * K + sidx) * D;
                int m_s = sidx & 3;            // (b*512+sidx)*769 mod 4
                const float4* f4src = (const float4*)(cand + sbase - m_s);
                #pragma unroll
                for (int c4 = lane; c4 < 192; c4 += 32)
                    *(float4*)&buf[warp][4 * c4] = __ldg(f4src + c4);
                if (lane <= m_s)
                    buf[warp][768 + lane] = __ldg(cand + sbase + 768 - m_s + lane);
                __syncwarp();

                float* dst = out_hard + ((size_t)b * TOPK + j) * D;
                int m_d = j & 3;               // (b*64+j)*769 mod 4
                int h = (4 - m_d) & 3;
                if (lane < h) dst[lane] = buf[warp][lane + m_s];
                int nd4 = (D - h) >> 2;
                float4* f4dst = (float4*)(dst + h);
                #pragma unroll
                for (int c4 = lane; c4 < nd4; c4 += 32) {
                    int e0 = h + 4 * c4 + m_s;
                    float4 v = { buf[warp][e0],     buf[warp][e0 + 1],
                                 buf[warp][e0 + 2], buf[warp][e0 + 3] };
                    f4dst[c4] = v;
                }
                int rem = (D - h) & 3;
                if (lane < rem) {
                    int e = h + 4 * nd4 + lane;
                    dst[e] = buf[warp][e + m_s];
                }
                __syncwarp();
            }

            __syncthreads();
            if (tid == 0) g_cnt[b] = 0;        // reset for next graph replay
            __syncthreads();
        }
    }
}

// ---------------------------------------------------------------------------
extern "C" void kernel_launch(void* const* d_in, const int* in_sizes, int n_in,
                              void* d_out, int out_size) {
    const float* anchor = (const float*)d_in[0];  // (B, E)
    const float* neg    = (const float*)d_in[1];  // (B, K, E)
    const float* cand   = (const float*)d_in[2];  // (B, K, D)
    float* out        = (float*)d_out;
    float* out_hard   = out;                          // (B, TOPK, D)
    float* out_scores = out + (size_t)B * TOPK * D;   // (B, TOPK)

    k_anchor<<<4, 256>>>(anchor);
    k_pipe<<<GRID_PIPE, 256>>>(neg, cand, out_hard, out_scores);
}

// round 11
// speedup vs baseline: 1.3027x; 1.1135x over previous
#include <cuda_runtime.h>
#include <cstddef>
#include <cstdint>

#define EPS 1e-8f

static constexpr int B    = 1024;
static constexpr int K    = 512;
static constexpr int E    = 64;
static constexpr int D    = 769;
static constexpr int TOPK = 64;

typedef unsigned long long u64;

__device__ float g_aw[B * E];
__device__ float g_la[B * E];
__device__ float g_scores[B * K];
__device__ int   g_idx[B * TOPK];

// ---------------------------------------------------------------------------
// Packed f32x2 primitives (Blackwell). Each is two independent IEEE rn f32
// ops -> bit-identical per lane to the scalar __fadd_rn/__fmul_rn/fmaf.
// ---------------------------------------------------------------------------
__device__ __forceinline__ u64 pk2(float lo, float hi) {
    u64 r; asm("mov.b64 %0, {%1, %2};" : "=l"(r) : "f"(lo), "f"(hi)); return r;
}
__device__ __forceinline__ void upk2(u64 v, float& lo, float& hi) {
    asm("mov.b64 {%0, %1}, %2;" : "=f"(lo), "=f"(hi) : "l"(v));
}
__device__ __forceinline__ u64 add2(u64 a, u64 b) {
    u64 r; asm("add.rn.f32x2 %0, %1, %2;" : "=l"(r) : "l"(a), "l"(b)); return r;
}
__device__ __forceinline__ u64 mul2(u64 a, u64 b) {
    u64 r; asm("mul.rn.f32x2 %0, %1, %2;" : "=l"(r) : "l"(a), "l"(b)); return r;
}
__device__ __forceinline__ u64 fma2(u64 a, u64 b, u64 c) {
    u64 r; asm("fma.rn.f32x2 %0, %1, %2, %3;" : "=l"(r) : "l"(a), "l"(b), "l"(c)); return r;
}

// ---------------------------------------------------------------------------
// Scalar XLA-CPU log (Eigen plog / Cephes, no FMA) — proven bit-exact. Used
// by the (tiny) anchor kernel. DO NOT MODIFY.
// ---------------------------------------------------------------------------
__device__ __forceinline__ float xla_logf(float xin) {
    float x = fmaxf(xin, __uint_as_float(0x00800000u));
    uint32_t bits = __float_as_uint(x);
    int emm0 = (int)(bits >> 23) - 126;
    float e = (float)emm0;
    float m = __uint_as_float((bits & 0x807fffffu) | 0x3f000000u);
    bool mask = m < __uint_as_float(0x3f3504f3u);
    float tmp = mask ? m : 0.0f;
    float xx = __fadd_rn(__fsub_rn(m, 1.0f), tmp);
    e = __fsub_rn(e, mask ? 1.0f : 0.0f);

    float z = __fmul_rn(xx, xx);
    float y = 7.0376836292e-2f;
    y = __fadd_rn(__fmul_rn(y, xx), -1.1514610310e-1f);
    y = __fadd_rn(__fmul_rn(y, xx),  1.1676998740e-1f);
    y = __fadd_rn(__fmul_rn(y, xx), -1.2420140846e-1f);
    y = __fadd_rn(__fmul_rn(y, xx),  1.4249322787e-1f);
    y = __fadd_rn(__fmul_rn(y, xx), -1.6668057665e-1f);
    y = __fadd_rn(__fmul_rn(y, xx),  2.0000714765e-1f);
    y = __fadd_rn(__fmul_rn(y, xx), -2.4999993993e-1f);
    y = __fadd_rn(__fmul_rn(y, xx),  3.3333331174e-1f);
    y = __fmul_rn(y, xx);
    y = __fmul_rn(y, z);
    y = __fadd_rn(y, __fmul_rn(e, -2.12194440e-4f));
    y = __fsub_rn(y, __fmul_rn(z, 0.5f));
    float r = __fadd_rn(xx, y);
    r = __fadd_rn(r, __fmul_rn(e, 0.693359375f));
    return r;
}

// ---------------------------------------------------------------------------
// Packed XLA-CPU log: two elements per call, bit-identical per lane to
// xla_logf. Inputs are always >= 1e-8 (normal), so the fmax clamp is an
// identity and is dropped. Exact identities: sub(a,b)=add(a,-b);
// mul(z,-0.5) = -(z*0.5); integer exponent adjust before I2F.
// ---------------------------------------------------------------------------
__device__ __forceinline__ u64 xla_logf_x2(u64 x01) {
    float x0, x1; upk2(x01, x0, x1);
    uint32_t b0 = __float_as_uint(x0), b1 = __float_as_uint(x1);
    int e0i = (int)(b0 >> 23) - 126;
    int e1i = (int)(b1 >> 23) - 126;
    float m0 = __uint_as_float((b0 & 0x807fffffu) | 0x3f000000u);
    float m1 = __uint_as_float((b1 & 0x807fffffu) | 0x3f000000u);
    const float SQ = __uint_as_float(0x3f3504f3u);
    bool k0 = m0 < SQ, k1 = m1 < SQ;
    float t0 = k0 ? m0 : 0.0f;
    float t1 = k1 ? m1 : 0.0f;
    if (k0) e0i -= 1;
    if (k1) e1i -= 1;
    u64 m01 = pk2(m0, m1);
    u64 t01 = pk2(t0, t1);
    u64 e01 = pk2((float)e0i, (float)e1i);

    u64 xx = add2(add2(m01, pk2(-1.0f, -1.0f)), t01);
    u64 z  = mul2(xx, xx);
    u64 y  = pk2(7.0376836292e-2f, 7.0376836292e-2f);
    y = add2(mul2(y, xx), pk2(-1.1514610310e-1f, -1.1514610310e-1f));
    y = add2(mul2(y, xx), pk2( 1.1676998740e-1f,  1.1676998740e-1f));
    y = add2(mul2(y, xx), pk2(-1.2420140846e-1f, -1.2420140846e-1f));
    y = add2(mul2(y, xx), pk2( 1.4249322787e-1f,  1.4249322787e-1f));
    y = add2(mul2(y, xx), pk2(-1.6668057665e-1f, -1.6668057665e-1f));
    y = add2(mul2(y, xx), pk2( 2.0000714765e-1f,  2.0000714765e-1f));
    y = add2(mul2(y, xx), pk2(-2.4999993993e-1f, -2.4999993993e-1f));
    y = add2(mul2(y, xx), pk2( 3.3333331174e-1f,  3.3333331174e-1f));
    y = mul2(y, xx);
    y = mul2(y, z);
    y = add2(y, mul2(e01, pk2(-2.12194440e-4f, -2.12194440e-4f)));
    y = add2(y, mul2(z,   pk2(-0.5f, -0.5f)));
    u64 r = add2(xx, y);
    r = add2(r, mul2(e01, pk2(0.693359375f, 0.693359375f)));
    return r;
}

#define NEON_HORIZ(a0, a1, a2, a3) __fadd_rn(__fadd_rn(a0, a2), __fadd_rn(a1, a3))

// ---------------------------------------------------------------------------
// K1: anchor rows (scalar, proven, unchanged).
// ---------------------------------------------------------------------------
__global__ __launch_bounds__(256) void k_anchor(const float* __restrict__ anchor) {
    int b = blockIdx.x * blockDim.x + threadIdx.x;
    if (b >= B) return;
    const float4* row = (const float4*)(anchor + b * E);
    float4 vv[16];
    float a0 = 0.f, a1 = 0.f, a2 = 0.f, a3 = 0.f;
    #pragma unroll
    for (int c = 0; c < 16; c++) {
        vv[c] = __ldg(row + c);
        a0 = __fadd_rn(a0, __fadd_rn(vv[c].x, EPS));
        a1 = __fadd_rn(a1, __fadd_rn(vv[c].y, EPS));
        a2 = __fadd_rn(a2, __fadd_rn(vv[c].z, EPS));
        a3 = __fadd_rn(a3, __fadd_rn(vv[c].w, EPS));
    }
    float S = NEON_HORIZ(a0, a1, a2, a3);
    const float* vf = (const float*)vv;
    #pragma unroll
    for (int e = 0; e < E; e++) {
        float a = __fdiv_rn(__fadd_rn(vf[e], EPS), S);
        g_aw[b * E + e] = a;
        g_la[b * E + e] = xla_logf(__fadd_rn(a, EPS));
    }
}

// ---------------------------------------------------------------------------
// K2: confusion scores, packed-f32x2. One thread per (b,k).
// Division nn = ne/S replaced by hoisted __frcp_rn(S) + Markstein
// (q0 = rn(ne*y); r = fma(-S,q0,ne); q = fma(r,y,q0)) — correctly rounded,
// bit-equal to div.rn for all-normal operands (S in ~[20,44], ne in
// [1e-8, 1.2]). All other fp ops are packed rn, per-lane identical.
// ---------------------------------------------------------------------------
__global__ __launch_bounds__(256, 3) void k_scores(const float* __restrict__ neg) {
    __shared__ u64 s_a64[E / 2], s_la64[E / 2];
    int b = blockIdx.x >> 1;
    int k = ((blockIdx.x & 1) << 8) + threadIdx.x;
    if (threadIdx.x < E / 2) {
        const float* pa = &g_aw[b * E + 2 * threadIdx.x];
        const float* pl = &g_la[b * E + 2 * threadIdx.x];
        s_a64[threadIdx.x]  = pk2(__ldg(pa), __ldg(pa + 1));
        s_la64[threadIdx.x] = pk2(__ldg(pl), __ldg(pl + 1));
    }
    __syncthreads();

    const u64* row = (const u64*)(neg + ((size_t)b * K + k) * E);
    const u64 EPS2 = pk2(EPS, EPS);

    // pass 1: row sum (packed NEON accumulators; asm loads avoid CSE)
    u64 acc01 = 0ull, acc23 = 0ull;   // (+0,+0)
    #pragma unroll
    for (int c = 0; c < 16; c++) {
        u64 r01, r23;
        asm volatile("ld.global.nc.v2.u64 {%0, %1}, [%2];"
                     : "=l"(r01), "=l"(r23) : "l"(row + 2 * c));
        acc01 = add2(acc01, add2(r01, EPS2));
        acc23 = add2(acc23, add2(r23, EPS2));
    }
    float h02, h13;
    upk2(add2(acc01, acc23), h02, h13);       // (a0+a2, a1+a3)
    float S = __fadd_rn(h02, h13);

    float yr = __frcp_rn(S);                  // correctly-rounded 1/S, hoisted
    const u64 yy    = pk2(yr, yr);
    const u64 negS2 = pk2(-S, -S);

    // pass 2: KL accumulation (packed)
    u64 k01 = 0ull, k23 = 0ull;
    #pragma unroll 4
    for (int c = 0; c < 16; c++) {
        ulonglong2 rv = __ldg((const ulonglong2*)(row + 2 * c));
        u64 ne01 = add2(rv.x, EPS2);
        u64 ne23 = add2(rv.y, EPS2);
        // Markstein correctly-rounded division by S
        u64 q01 = mul2(ne01, yy);
        q01 = fma2(fma2(negS2, q01, ne01), yy, q01);
        u64 q23 = mul2(ne23, yy);
        q23 = fma2(fma2(negS2, q23, ne23), yy, q23);

        u64 ln01 = xla_logf_x2(add2(q01, EPS2));
        u64 ln23 = xla_logf_x2(add2(q23, EPS2));

        u64 la01 = s_la64[2 * c],     la23 = s_la64[2 * c + 1];
        u64 a01  = s_a64[2 * c],      a23  = s_a64[2 * c + 1];
        const u64 NEG1 = pk2(-1.0f, -1.0f);
        u64 d01 = add2(la01, mul2(ln01, NEG1));   // la - ln (exact)
        u64 d23 = add2(la23, mul2(ln23, NEG1));
        k01 = add2(k01, mul2(a01, d01));
        k23 = add2(k23, mul2(a23, d23));
    }
    float g02, g13;
    upk2(add2(k01, k23), g02, g13);
    g_scores[b * K + k] = -__fadd_rn(g02, g13);
}

// ---------------------------------------------------------------------------
// K3: per-row top-64 via bitonic sort of 512 (desc, ties -> lower index).
// ---------------------------------------------------------------------------
__global__ __launch_bounds__(512) void k_topk(float* __restrict__ out_scores) {
    __shared__ float ss[K];
    __shared__ int   si[K];
    int b = blockIdx.x, tid = threadIdx.x;
    ss[tid] = g_scores[b * K + tid];
    si[tid] = tid;
    for (int sz = 2; sz <= K; sz <<= 1) {
        for (int j = sz >> 1; j > 0; j >>= 1) {
            __syncthreads();
            int ixj = tid ^ j;
            if (ixj > tid) {
                bool desc = ((tid & sz) == 0);
                float s1 = ss[tid], s2 = ss[ixj];
                int   i1 = si[tid], i2 = si[ixj];
                bool g = (s1 > s2) || (s1 == s2 && i1 < i2);
                if (g != desc) {
                    ss[tid] = s2; ss[ixj] = s1;
                    si[tid] = i2; si[ixj] = i1;
                }
            }
        }
    }
    __syncthreads();
    if (tid < TOPK) {
        out_scores[b * TOPK + tid] = ss[tid];
        g_idx[b * TOPK + tid]      = si[tid];
    }
}

// ---------------------------------------------------------------------------
// K4: gather selected candidate rows (769 f32) — proven coalesced copy.
// ---------------------------------------------------------------------------
__global__ __launch_bounds__(128) void k_gather(
    const float* __restrict__ cand, float* __restrict__ out_hard)
{
    int blk = blockIdx.x;
    int b = blk >> 6, j = blk & (TOPK - 1);
    int idx = g_idx[b * TOPK + j];
    const float* __restrict__ src = cand + ((size_t)b * K + idx) * D;
    float* __restrict__ dst = out_hard + ((size_t)b * TOPK + j) * D;
    #pragma unroll
    for (int i = threadIdx.x; i < D; i += 128)
        dst[i] = __ldg(src + i);
}

// ---------------------------------------------------------------------------
extern "C" void kernel_launch(void* const* d_in, const int* in_sizes, int n_in,
                              void* d_out, int out_size) {
    const float* anchor = (const float*)d_in[0];  // (B, E)
    const float* neg    = (const float*)d_in[1];  // (B, K, E)
    const float* cand   = (const float*)d_in[2];  // (B, K, D)
    float* out        = (float*)d_out;
    float* out_hard   = out;                          // (B, TOPK, D)
    float* out_scores = out + (size_t)B * TOPK * D;   // (B, TOPK)

    k_anchor<<<4, 256>>>(anchor);
    k_scores<<<B * 2, 256>>>(neg);
    k_topk<<<B, 512>>>(out_scores);
    k_gather<<<B * TOPK, 128>>>(cand, out_hard);
}